// round 11
// baseline (speedup 1.0000x reference)
#include <cuda_runtime.h>
#include <cstdint>
#include <cstddef>

#define T_N   1024
#define B_N   64
#define V_N   32000
#define H_N   512

#define GC    32                 // col-members per group
#define GB    4                  // independent batch-groups
#define GRID_R (GC * GB)         // 128 CTAs, 1 per SM
#define BPG   16                 // batches per group
#define CPM   16                 // cols per member
#define NTHR  256

// ---------------- persistent device scratch ----------------
__device__ float    g_embW0[(size_t)V_N * H_N];   // emb @ Wih0^T + bih0 + bhh0
__device__ float    g_h0[2][B_N * H_N];
__device__ float    g_h1[2][B_N * H_N];
__device__ unsigned g_flag[GRID_R * 8];           // per-CTA step flags (32B stride)

// ---------------- reset: deterministic per launch / graph replay ----------------
__global__ void reset_kernel() {
    int i = blockIdx.x * blockDim.x + threadIdx.x;
    if (i < B_N * H_N) {
        g_h0[0][i] = 0.f; g_h0[1][i] = 0.f;
        g_h1[0][i] = 0.f; g_h1[1][i] = 0.f;
    }
    if (i < GRID_R * 8) g_flag[i] = 0u;
}

// ---------------- embW0[v][h] = emb[v]·Wih0[h] + bih0[h] + bhh0[h] ----------------
__global__ __launch_bounds__(256) void embw_kernel(const float* __restrict__ A,
                                                   const float* __restrict__ W,
                                                   const float* __restrict__ bih,
                                                   const float* __restrict__ bhh) {
    __shared__ float As[8][132];
    __shared__ float Ws[8][132];
    const int tid   = threadIdx.x;
    const int hBase = blockIdx.x * 128;
    const int vBase = blockIdx.y * 128;
    const int lRow  = tid >> 1;
    const int lCol  = (tid & 1) * 4;
    const int tx    = tid & 15;
    const int ty    = tid >> 4;

    const float4* Ap = (const float4*)(A + (size_t)(vBase + lRow) * H_N + lCol);
    const float4* Wp = (const float4*)(W + (size_t)(hBase + lRow) * H_N + lCol);

    float acc[8][8];
#pragma unroll
    for (int i = 0; i < 8; i++)
#pragma unroll
        for (int j = 0; j < 8; j++) acc[i][j] = 0.f;

    float4 av = Ap[0];
    float4 wv = Wp[0];

    for (int k0 = 0; k0 < 512; k0 += 8) {
        __syncthreads();
        As[lCol + 0][lRow] = av.x; As[lCol + 1][lRow] = av.y;
        As[lCol + 2][lRow] = av.z; As[lCol + 3][lRow] = av.w;
        Ws[lCol + 0][lRow] = wv.x; Ws[lCol + 1][lRow] = wv.y;
        Ws[lCol + 2][lRow] = wv.z; Ws[lCol + 3][lRow] = wv.w;
        __syncthreads();
        if (k0 + 8 < 512) {
            av = Ap[(k0 + 8) >> 2];
            wv = Wp[(k0 + 8) >> 2];
        }
#pragma unroll
        for (int k = 0; k < 8; k++) {
            float a[8], w[8];
            *(float4*)&a[0] = *(const float4*)&As[k][ty * 8];
            *(float4*)&a[4] = *(const float4*)&As[k][ty * 8 + 4];
            *(float4*)&w[0] = *(const float4*)&Ws[k][tx * 8];
            *(float4*)&w[4] = *(const float4*)&Ws[k][tx * 8 + 4];
#pragma unroll
            for (int i = 0; i < 8; i++)
#pragma unroll
                for (int j = 0; j < 8; j++) acc[i][j] += a[i] * w[j];
        }
    }

#pragma unroll
    for (int i = 0; i < 8; i++) {
        const int v = vBase + ty * 8 + i;
        float* orow = &g_embW0[(size_t)v * H_N + hBase + tx * 8];
        float o[8];
#pragma unroll
        for (int j = 0; j < 8; j++) {
            int h = hBase + tx * 8 + j;
            o[j] = acc[i][j] + __ldg(&bih[h]) + __ldg(&bhh[h]);
        }
        *(float4*)&orow[0] = *(float4*)&o[0];
        *(float4*)&orow[4] = *(float4*)&o[4];
    }
}

// ---------------- packed-fp32 helpers ----------------
typedef unsigned long long u64;
__device__ __forceinline__ u64 ffma2(u64 a, u64 b, u64 c) {
    u64 d;
    asm("fma.rn.f32x2 %0, %1, %2, %3;" : "=l"(d) : "l"(a), "l"(b), "l"(c));
    return d;
}
__device__ __forceinline__ float unpack_sum(u64 a) {
    float lo, hi;
    asm("mov.b64 {%0, %1}, %2;" : "=f"(lo), "=f"(hi) : "l"(a));
    return lo + hi;
}

// ---------------- persistent recurrence kernel (lag-3 h1 schedule) ----------------
// SMEM floats: W0[8192] WA[8192] WB[8192] Hs0[2][8192] Hs1[8192] Rs0[2304] Rs1[2304] b1[16]
#define OFF_W0  0
#define OFF_WA  8192
#define OFF_WB  16384
#define OFF_H0A 24576
#define OFF_H0B 32768
#define OFF_H1  40960
#define OFF_R0  49152
#define OFF_R1  (OFF_R0 + 2304)
#define OFF_B1  (OFF_R1 + 2304)
#define SMEM_FLOATS (OFF_B1 + 16)
#define SMEM_BYTES  (SMEM_FLOATS * 4)       // ~215.1 KB

__global__ __launch_bounds__(NTHR, 1) void rnn_kernel(const int*   __restrict__ input,
                                                      const float* __restrict__ Whh0,
                                                      const float* __restrict__ Wih1,
                                                      const float* __restrict__ Whh1,
                                                      const float* __restrict__ bih1,
                                                      const float* __restrict__ bhh1,
                                                      float*       __restrict__ out) {
    extern __shared__ float smem[];
    float* W0s = smem + OFF_W0;
    float* WAs = smem + OFF_WA;
    float* WBs = smem + OFF_WB;
    float* Rs0 = smem + OFF_R0;
    float* Rs1 = smem + OFF_R1;
    float* b1s = smem + OFF_B1;

    const int tid  = threadIdx.x;
    const int cid  = blockIdx.x;
    const int m    = cid & (GC - 1);   // member: cols [m*16, m*16+16)
    const int grp  = cid >> 5;         // group: batches [grp*16, grp*16+16)
    const int gb16 = grp * BPG;
    const int w    = tid >> 5;
    const int lane = tid & 31;
    const int o    = w >> 2;           // batch-oct (0..1)
    const int cq   = w & 3;            // col-quad  (0..3)

    // ---- preload weight slices: rows [m*16, m*16+16) ----
    {
        const float4* s0 = (const float4*)Whh0 + (size_t)m * 2048;
        const float4* s1 = (const float4*)Wih1 + (size_t)m * 2048;
        const float4* s2 = (const float4*)Whh1 + (size_t)m * 2048;
        float4* d0 = (float4*)W0s; float4* d1 = (float4*)WAs; float4* d2 = (float4*)WBs;
        for (int r = tid; r < 2048; r += NTHR) {
            d0[r] = __ldg(&s0[r]);
            d1[r] = __ldg(&s1[r]);
            d2[r] = __ldg(&s2[r]);
        }
        if (tid < CPM) b1s[tid] = __ldg(&bih1[m * CPM + tid]) + __ldg(&bhh1[m * CPM + tid]);
    }
    // ---- prologue: Hs0 buffer 0 must read as h0[-2] = 0 at s=1 ----
    for (int i = tid; i < 8192; i += NTHR) smem[OFF_H0A + i] = 0.f;
    __syncthreads();

    // read-phase decode: thread tid owns output tid = b*16 + c
    const int b_out  = gb16 + (tid >> 4);
    const int c_glob = m * CPM + (tid & 15);

    const ulonglong2* W0u = (const ulonglong2*)W0s;
    const ulonglong2* WAu = (const ulonglong2*)WAs;
    const ulonglong2* WBu = (const ulonglong2*)WBs;
    const ulonglong2* H0u[2] = { (const ulonglong2*)(smem + OFF_H0A),
                                 (const ulonglong2*)(smem + OFF_H0B) };
    const ulonglong2* H1u = (const ulonglong2*)(smem + OFF_H1);
    const unsigned sdh0[2] = { (unsigned)__cvta_generic_to_shared(smem + OFF_H0A),
                               (unsigned)__cvta_generic_to_shared(smem + OFF_H0B) };
    const unsigned sdh1 = (unsigned)__cvta_generic_to_shared(smem + OFF_H1);

    u64 acc0[8][4], accA[8][4];

    // one pass chunk (k-quarter J): ACC += Wu-rows · Hu
#define MMA_PASS(Wu, Hu, ACC, J)                                                 \
    {                                                                            \
        ulonglong2 wq[4];                                                        \
        _Pragma("unroll")                                                        \
        for (int c = 0; c < 4; c++)                                              \
            wq[c] = (Wu)[(cq * 4 + c) * 128 + (J) * 32 + lane];                  \
        _Pragma("unroll")                                                        \
        for (int i = 0; i < 8; i++) {                                            \
            ulonglong2 hv = (Hu)[(o * 8 + i) * 128 + (J) * 32 + lane];           \
            _Pragma("unroll")                                                    \
            for (int c = 0; c < 4; c++) {                                        \
                ACC[i][c] = ffma2(hv.x, wq[c].x, ACC[i][c]);                     \
                ACC[i][c] = ffma2(hv.y, wq[c].y, ACC[i][c]);                     \
            }                                                                    \
        }                                                                        \
    }

    // shfl16+shfl8 pre-reduce -> RS rows of 8 (stride 9)
#define REDUCE8(RS, ACC)                                                         \
    _Pragma("unroll")                                                            \
    for (int i = 0; i < 8; i++)                                                  \
        _Pragma("unroll")                                                        \
        for (int c = 0; c < 4; c++) {                                            \
            float v = unpack_sum(ACC[i][c]);                                     \
            v += __shfl_xor_sync(0xffffffffu, v, 16);                            \
            v += __shfl_xor_sync(0xffffffffu, v, 8);                             \
            if (lane < 8)                                                        \
                (RS)[((o * 8 + i) * 16 + cq * 4 + c) * 9 + lane] = v;            \
        }

    // stage a full 16x512 state block (8 f4/thread), no commit here
#define STAGE_BUF(SD, SRC)                                                       \
    {                                                                            \
        _Pragma("unroll")                                                        \
        for (int r = 0; r < 8; r++) {                                            \
            int l   = r * NTHR + tid;          /* 0..2047 float4 */              \
            int b_l = l >> 7;                                                    \
            int c4  = l & 127;                                                   \
            size_t srcf4 = (size_t)(gb16 + b_l) * 128 + c4;                      \
            asm volatile("cp.async.cg.shared.global [%0], [%1], 16;\n"           \
                         :: "r"((SD) + l * 16), "l"((SRC) + srcf4 * 4));         \
        }                                                                        \
    }

    for (int s = 1; s <= T_N + 2; s++) {
        const bool doH0 = (s <= T_N);
        const bool doH1 = (s >= 3);
        const int  cur  = s & 1;           // Hs0 buffer staged this step (h0[s-2])
        const int  prv  = cur ^ 1;         // previous step's Hs0 (h0[s-3])

        // ---- gather input-projection value early (independent) ----
        float xw = 0.f;
        if (doH0) {
            int tok = __ldg(&input[(s - 1) * B_N + b_out]);
            xw = __ldcg(&g_embW0[(size_t)tok * H_N + c_glob]);
        }

        // ---- barrier: wait 32 members' flags >= s-1 ----
        if (w == 0) {
            const unsigned* fp = &g_flag[(grp * GC + lane) * 8];
            unsigned v;
            do {
                asm volatile("ld.relaxed.gpu.global.u32 %0, [%1];"
                             : "=r"(v) : "l"(fp) : "memory");
            } while (__any_sync(0xffffffffu, v < (unsigned)(s - 1)));
            __threadfence();
        }
        __syncthreads();

        // ---- stage h0[s-2] -> Hs0[cur], h1[s-4] -> Hs1 (one commit group) ----
        STAGE_BUF(sdh0[cur], g_h0[s & 1])
        STAGE_BUF(sdh1,      g_h1[s & 1])
        asm volatile("cp.async.commit_group;\n");

#pragma unroll
        for (int i = 0; i < 8; i++)
#pragma unroll
            for (int c = 0; c < 4; c++) { acc0[i][c] = 0ull; accA[i][c] = 0ull; }

        // ---- pass1b: Wih1 · h0[s-3] from PREVIOUS Hs0 (hides stage flight) ----
        MMA_PASS(WAu, H0u[prv], accA, 0)
        MMA_PASS(WAu, H0u[prv], accA, 1)
        MMA_PASS(WAu, H0u[prv], accA, 2)
        MMA_PASS(WAu, H0u[prv], accA, 3)

        // ---- staged data ready ----
        asm volatile("cp.async.wait_group 0;\n" ::: "memory");
        __syncthreads();

        // ---- pass1: Whh0 · h0[s-2] ----
        MMA_PASS(W0u, H0u[cur], acc0, 0)
        MMA_PASS(W0u, H0u[cur], acc0, 1)
        MMA_PASS(W0u, H0u[cur], acc0, 2)
        MMA_PASS(W0u, H0u[cur], acc0, 3)

        // ---- pass2: Whh1 · h1[s-4] ----
        MMA_PASS(WBu, H1u, accA, 0)
        MMA_PASS(WBu, H1u, accA, 1)
        MMA_PASS(WBu, H1u, accA, 2)
        MMA_PASS(WBu, H1u, accA, 3)

        // ---- merged reduce (one sync) ----
        REDUCE8(Rs0, acc0)
        REDUCE8(Rs1, accA)
        __syncthreads();

        // ---- epilogues ----
        if (doH0) {
            float ssum = 0.f;
#pragma unroll
            for (int l = 0; l < 8; l++) ssum += Rs0[tid * 9 + l];
            __stcg(&g_h0[(s - 1) & 1][b_out * H_N + c_glob], tanhf(ssum + xw));
        }
        if (doH1) {
            float ssum = 0.f;
#pragma unroll
            for (int l = 0; l < 8; l++) ssum += Rs1[tid * 9 + l];
            float v = tanhf(ssum + b1s[tid & 15]);
            __stcg(&g_h1[(s + 1) & 1][b_out * H_N + c_glob], v);
            if (s == T_N + 2) __stcg(&out[b_out * H_N + c_glob], v);
        }

        // ---- publish step ----
        __syncthreads();
        if (tid == 0)
            asm volatile("st.release.gpu.global.u32 [%0], %1;"
                         :: "l"(&g_flag[cid * 8]), "r"((unsigned)s) : "memory");
    }
#undef MMA_PASS
#undef REDUCE8
#undef STAGE_BUF
}

// ---------------- launch ----------------
extern "C" void kernel_launch(void* const* d_in, const int* in_sizes, int n_in,
                              void* d_out, int out_size) {
    const int*   input = (const int*)  d_in[0];
    const float* emb   = (const float*)d_in[1];
    const float* Wih0  = (const float*)d_in[2];
    const float* Whh0  = (const float*)d_in[3];
    const float* bih0  = (const float*)d_in[4];
    const float* bhh0  = (const float*)d_in[5];
    const float* Wih1  = (const float*)d_in[6];
    const float* Whh1  = (const float*)d_in[7];
    const float* bih1  = (const float*)d_in[8];
    const float* bhh1  = (const float*)d_in[9];
    float* out = (float*)d_out;

    cudaFuncSetAttribute(rnn_kernel, cudaFuncAttributeMaxDynamicSharedMemorySize, SMEM_BYTES);

    reset_kernel<<<(B_N * H_N + 255) / 256, 256>>>();
    embw_kernel<<<dim3(H_N / 128, V_N / 128), 256>>>(emb, Wih0, bih0, bhh0);
    rnn_kernel<<<GRID_R, NTHR, SMEM_BYTES>>>(input, Whh0, Wih1, Whh1, bih1, bhh1, out);
}

// round 12
// speedup vs baseline: 1.2510x; 1.2510x over previous
#include <cuda_runtime.h>
#include <cstdint>
#include <cstddef>

#define T_N   1024
#define B_N   64
#define V_N   32000
#define H_N   512

#define GC    32                 // col-members per group
#define GB    4                  // independent batch-groups
#define GRID_R (GC * GB)         // 128 CTAs, 1 per SM
#define BPG   16                 // batches per group
#define CPM   16                 // cols per member
#define NTHR  256
#define NSTEP (T_N + 3)

// ---------------- persistent device scratch ----------------
__device__ float    g_embW0[(size_t)V_N * H_N];   // emb @ Wih0^T + bih0 + bhh0
__device__ float    g_h0[2][B_N * H_N];
__device__ float    g_h1[2][B_N * H_N];
__device__ unsigned g_bar[GB][NSTEP];             // per-(group,step) arrival counters

// ---------------- reset: deterministic per launch / graph replay ----------------
__global__ void reset_kernel() {
    int i = blockIdx.x * blockDim.x + threadIdx.x;
    if (i < B_N * H_N) {
        g_h0[0][i] = 0.f; g_h0[1][i] = 0.f;
        g_h1[0][i] = 0.f; g_h1[1][i] = 0.f;
    }
    if (i < GB * NSTEP) {
        int st = i % NSTEP;
        ((unsigned*)g_bar)[i] = (st == 0) ? (unsigned)GC : 0u;  // step-0 pre-passed
    }
}

// ---------------- embW0[v][h] = emb[v]·Wih0[h] + bih0[h] + bhh0[h] ----------------
__global__ __launch_bounds__(256) void embw_kernel(const float* __restrict__ A,
                                                   const float* __restrict__ W,
                                                   const float* __restrict__ bih,
                                                   const float* __restrict__ bhh) {
    __shared__ float As[8][132];
    __shared__ float Ws[8][132];
    const int tid   = threadIdx.x;
    const int hBase = blockIdx.x * 128;
    const int vBase = blockIdx.y * 128;
    const int lRow  = tid >> 1;
    const int lCol  = (tid & 1) * 4;
    const int tx    = tid & 15;
    const int ty    = tid >> 4;

    const float4* Ap = (const float4*)(A + (size_t)(vBase + lRow) * H_N + lCol);
    const float4* Wp = (const float4*)(W + (size_t)(hBase + lRow) * H_N + lCol);

    float acc[8][8];
#pragma unroll
    for (int i = 0; i < 8; i++)
#pragma unroll
        for (int j = 0; j < 8; j++) acc[i][j] = 0.f;

    float4 av = Ap[0];
    float4 wv = Wp[0];

    for (int k0 = 0; k0 < 512; k0 += 8) {
        __syncthreads();
        As[lCol + 0][lRow] = av.x; As[lCol + 1][lRow] = av.y;
        As[lCol + 2][lRow] = av.z; As[lCol + 3][lRow] = av.w;
        Ws[lCol + 0][lRow] = wv.x; Ws[lCol + 1][lRow] = wv.y;
        Ws[lCol + 2][lRow] = wv.z; Ws[lCol + 3][lRow] = wv.w;
        __syncthreads();
        if (k0 + 8 < 512) {
            av = Ap[(k0 + 8) >> 2];
            wv = Wp[(k0 + 8) >> 2];
        }
#pragma unroll
        for (int k = 0; k < 8; k++) {
            float a[8], w[8];
            *(float4*)&a[0] = *(const float4*)&As[k][ty * 8];
            *(float4*)&a[4] = *(const float4*)&As[k][ty * 8 + 4];
            *(float4*)&w[0] = *(const float4*)&Ws[k][tx * 8];
            *(float4*)&w[4] = *(const float4*)&Ws[k][tx * 8 + 4];
#pragma unroll
            for (int i = 0; i < 8; i++)
#pragma unroll
                for (int j = 0; j < 8; j++) acc[i][j] += a[i] * w[j];
        }
    }

#pragma unroll
    for (int i = 0; i < 8; i++) {
        const int v = vBase + ty * 8 + i;
        float* orow = &g_embW0[(size_t)v * H_N + hBase + tx * 8];
        float o[8];
#pragma unroll
        for (int j = 0; j < 8; j++) {
            int h = hBase + tx * 8 + j;
            o[j] = acc[i][j] + __ldg(&bih[h]) + __ldg(&bhh[h]);
        }
        *(float4*)&orow[0] = *(float4*)&o[0];
        *(float4*)&orow[4] = *(float4*)&o[4];
    }
}

// ---------------- packed-fp32 helpers ----------------
typedef unsigned long long u64;
__device__ __forceinline__ u64 ffma2(u64 a, u64 b, u64 c) {
    u64 d;
    asm("fma.rn.f32x2 %0, %1, %2, %3;" : "=l"(d) : "l"(a), "l"(b), "l"(c));
    return d;
}
__device__ __forceinline__ float unpack_sum(u64 a) {
    float lo, hi;
    asm("mov.b64 {%0, %1}, %2;" : "=f"(lo), "=f"(hi) : "l"(a));
    return lo + hi;
}

// ---------------- persistent recurrence kernel (R10 compute + lean sync) ----------------
// SMEM floats: W0[8192] WA[8192] WB[8192] Hs0[8192] Hs1[8192] Rs0[4352] Rs1[4352] b1[16]
#define OFF_W0 0
#define OFF_WA 8192
#define OFF_WB 16384
#define OFF_H0 24576
#define OFF_H1 32768
#define OFF_R0 40960
#define OFF_R1 (OFF_R0 + 4352)
#define OFF_B1 (OFF_R1 + 4352)
#define SMEM_FLOATS (OFF_B1 + 16)
#define SMEM_BYTES  (SMEM_FLOATS * 4)       // ~198.7 KB

__global__ __launch_bounds__(NTHR, 1) void rnn_kernel(const int*   __restrict__ input,
                                                      const float* __restrict__ Whh0,
                                                      const float* __restrict__ Wih1,
                                                      const float* __restrict__ Whh1,
                                                      const float* __restrict__ bih1,
                                                      const float* __restrict__ bhh1,
                                                      float*       __restrict__ out) {
    extern __shared__ float smem[];
    float* W0s = smem + OFF_W0;
    float* WAs = smem + OFF_WA;
    float* WBs = smem + OFF_WB;
    float* Rs0 = smem + OFF_R0;
    float* Rs1 = smem + OFF_R1;
    float* b1s = smem + OFF_B1;

    const int tid  = threadIdx.x;
    const int cid  = blockIdx.x;
    const int m    = cid & (GC - 1);   // member: cols [m*16, m*16+16)
    const int grp  = cid >> 5;         // group: batches [grp*16, grp*16+16)
    const int gb16 = grp * BPG;
    const int w    = tid >> 5;
    const int lane = tid & 31;
    const int o    = w >> 2;           // batch-oct (0..1)
    const int cq   = w & 3;            // col-quad  (0..3)

    // ---- preload weight slices: rows [m*16, m*16+16) ----
    {
        const float4* s0 = (const float4*)Whh0 + (size_t)m * 2048;
        const float4* s1 = (const float4*)Wih1 + (size_t)m * 2048;
        const float4* s2 = (const float4*)Whh1 + (size_t)m * 2048;
        float4* d0 = (float4*)W0s; float4* d1 = (float4*)WAs; float4* d2 = (float4*)WBs;
        for (int r = tid; r < 2048; r += NTHR) {
            d0[r] = __ldg(&s0[r]);
            d1[r] = __ldg(&s1[r]);
            d2[r] = __ldg(&s2[r]);
        }
        if (tid < CPM) b1s[tid] = __ldg(&bih1[m * CPM + tid]) + __ldg(&bhh1[m * CPM + tid]);
    }
    __syncthreads();

    // read-phase decode: thread tid owns output tid = b*16 + c
    const int b_out  = gb16 + (tid >> 4);
    const int c_glob = m * CPM + (tid & 15);

    const ulonglong2* W0u = (const ulonglong2*)W0s;
    const ulonglong2* WAu = (const ulonglong2*)WAs;
    const ulonglong2* WBu = (const ulonglong2*)WBs;
    const ulonglong2* H0u = (const ulonglong2*)(smem + OFF_H0);
    const ulonglong2* H1u = (const ulonglong2*)(smem + OFF_H1);
    const unsigned sd0 = (unsigned)__cvta_generic_to_shared(smem + OFF_H0);
    const unsigned sd1 = (unsigned)__cvta_generic_to_shared(smem + OFF_H1);

    u64 acc0[8][4], accA[8][4];

    // fused pass-1 chunk (k-quarter J): Whh0 + Wih1 share every hv load
#define MMA1_CHUNK(J)                                                            \
    {                                                                            \
        ulonglong2 w0q[4], waq[4];                                               \
        _Pragma("unroll")                                                        \
        for (int c = 0; c < 4; c++) {                                            \
            int row = cq * 4 + c;                                                \
            w0q[c] = W0u[row * 128 + (J) * 32 + lane];                           \
            waq[c] = WAu[row * 128 + (J) * 32 + lane];                           \
        }                                                                        \
        _Pragma("unroll")                                                        \
        for (int i = 0; i < 8; i++) {                                            \
            ulonglong2 hv = H0u[(o * 8 + i) * 128 + (J) * 32 + lane];            \
            _Pragma("unroll")                                                    \
            for (int c = 0; c < 4; c++) {                                        \
                acc0[i][c] = ffma2(hv.x, w0q[c].x, acc0[i][c]);                  \
                acc0[i][c] = ffma2(hv.y, w0q[c].y, acc0[i][c]);                  \
                accA[i][c] = ffma2(hv.x, waq[c].x, accA[i][c]);                  \
                accA[i][c] = ffma2(hv.y, waq[c].y, accA[i][c]);                  \
            }                                                                    \
        }                                                                        \
    }

    // pass-2 chunk: Whh1 · h1[s-3] into accA
#define MMA2_CHUNK(J)                                                            \
    {                                                                            \
        ulonglong2 wbq[4];                                                       \
        _Pragma("unroll")                                                        \
        for (int c = 0; c < 4; c++)                                              \
            wbq[c] = WBu[(cq * 4 + c) * 128 + (J) * 32 + lane];                  \
        _Pragma("unroll")                                                        \
        for (int i = 0; i < 8; i++) {                                            \
            ulonglong2 hv = H1u[(o * 8 + i) * 128 + (J) * 32 + lane];            \
            _Pragma("unroll")                                                    \
            for (int c = 0; c < 4; c++) {                                        \
                accA[i][c] = ffma2(hv.x, wbq[c].x, accA[i][c]);                  \
                accA[i][c] = ffma2(hv.y, wbq[c].y, accA[i][c]);                  \
            }                                                                    \
        }                                                                        \
    }

    // shfl-16 pre-reduce ACC -> RS rows of 16 (stride 17, conflict-free)
#define REDUCE_TO(RS, ACC)                                                       \
    _Pragma("unroll")                                                            \
    for (int i = 0; i < 8; i++)                                                  \
        _Pragma("unroll")                                                        \
        for (int c = 0; c < 4; c++) {                                            \
            float v = unpack_sum(ACC[i][c]);                                     \
            v += __shfl_xor_sync(0xffffffffu, v, 16);                            \
            if (lane < 16)                                                       \
                (RS)[((o * 8 + i) * 16 + cq * 4 + c) * 17 + lane] = v;           \
        }

    // stage one k-half (Q=0/1) of a 16-row state block, commit as one group
#define STAGE_HALF(SD, SRC, Q)                                                   \
    {                                                                            \
        _Pragma("unroll")                                                        \
        for (int r = 0; r < 4; r++) {                                            \
            int l   = r * NTHR + tid;          /* 0..1023 f4 within half */      \
            int b_l = l >> 6;                                                    \
            int c4  = l & 63;                                                    \
            size_t srcf4 = (size_t)(gb16 + b_l) * 128 + (Q) * 64 + c4;           \
            asm volatile("cp.async.cg.shared.global [%0], [%1], 16;\n"           \
                         :: "r"((SD) + (b_l * 128 + (Q) * 64 + c4) * 16),        \
                            "l"((SRC) + srcf4 * 4));                             \
        }                                                                        \
        asm volatile("cp.async.commit_group;\n");                                \
    }

    // stage a full 16-row block as ONE commit group
#define STAGE_FULL(SD, SRC)                                                      \
    {                                                                            \
        _Pragma("unroll")                                                        \
        for (int r = 0; r < 8; r++) {                                            \
            int l   = r * NTHR + tid;          /* 0..2047 f4 */                  \
            int b_l = l >> 7;                                                    \
            int c4  = l & 127;                                                   \
            size_t srcf4 = (size_t)(gb16 + b_l) * 128 + c4;                      \
            asm volatile("cp.async.cg.shared.global [%0], [%1], 16;\n"           \
                         :: "r"((SD) + l * 16), "l"((SRC) + srcf4 * 4));         \
        }                                                                        \
        asm volatile("cp.async.commit_group;\n");                                \
    }

    for (int s = 1; s <= T_N + 1; s++) {
        const bool doH0 = (s <= T_N);
        const bool doH1 = (s >= 2);

        // ---- gather input-projection value early (independent) ----
        float xw = 0.f;
        if (doH0) {
            int tok = __ldg(&input[(s - 1) * B_N + b_out]);
            xw = __ldcg(&g_embW0[(size_t)tok * H_N + c_glob]);
        }

        // ---- barrier: single-counter wait (lane 0 polls one address) ----
        if (tid == 0) {
            const unsigned* bp = &g_bar[grp][s - 1];
            unsigned v;
            do {
                asm volatile("ld.acquire.gpu.global.u32 %0, [%1];"
                             : "=r"(v) : "l"(bp) : "memory");
            } while (v < (unsigned)GC);
        }
        __syncthreads();

        // ---- stage h0[s-2] (2 half-groups) and h1[s-3] (1 group) ----
        {
            const float* h0src = g_h0[s & 1];
            const float* h1src = g_h1[(s + 1) & 1];
            STAGE_HALF(sd0, h0src, 0)
            STAGE_HALF(sd0, h0src, 1)
            STAGE_FULL(sd1, h1src)
        }

#pragma unroll
        for (int i = 0; i < 8; i++)
#pragma unroll
            for (int c = 0; c < 4; c++) { acc0[i][c] = 0ull; accA[i][c] = 0ull; }

        // ---- pass 1 (fused Whh0 + Wih1 on h0[s-2]) ----
        asm volatile("cp.async.wait_group 2;\n" ::: "memory");
        __syncthreads();
        MMA1_CHUNK(0)
        MMA1_CHUNK(1)
        asm volatile("cp.async.wait_group 1;\n" ::: "memory");
        __syncthreads();
        MMA1_CHUNK(2)
        MMA1_CHUNK(3)

        // ---- pass 2 (Whh1 on h1[s-3]) ----
        asm volatile("cp.async.wait_group 0;\n" ::: "memory");
        __syncthreads();
        MMA2_CHUNK(0)
        MMA2_CHUNK(1)
        MMA2_CHUNK(2)
        MMA2_CHUNK(3)

        // ---- merged reduce (one sync for both) ----
        REDUCE_TO(Rs0, acc0)
        REDUCE_TO(Rs1, accA)
        __syncthreads();

        // ---- epilogues ----
        if (doH0) {
            float ssum = 0.f;
#pragma unroll
            for (int l = 0; l < 16; l++) ssum += Rs0[tid * 17 + l];
            __stcg(&g_h0[(s - 1) & 1][b_out * H_N + c_glob], tanhf(ssum + xw));
        }
        if (doH1) {
            float ssum = 0.f;
#pragma unroll
            for (int l = 0; l < 16; l++) ssum += Rs1[tid * 17 + l];
            float v = tanhf(ssum + b1s[tid & 15]);
            __stcg(&g_h1[s & 1][b_out * H_N + c_glob], v);
            if (s == T_N + 1) __stcg(&out[b_out * H_N + c_glob], v);
        }

        // ---- publish: one release-reduction on the group counter ----
        __syncthreads();
        if (tid == 0)
            asm volatile("red.release.gpu.global.add.u32 [%0], 1;"
                         :: "l"(&g_bar[grp][s]) : "memory");
    }
#undef MMA1_CHUNK
#undef MMA2_CHUNK
#undef REDUCE_TO
#undef STAGE_HALF
#undef STAGE_FULL
}

// ---------------- launch ----------------
extern "C" void kernel_launch(void* const* d_in, const int* in_sizes, int n_in,
                              void* d_out, int out_size) {
    const int*   input = (const int*)  d_in[0];
    const float* emb   = (const float*)d_in[1];
    const float* Wih0  = (const float*)d_in[2];
    const float* Whh0  = (const float*)d_in[3];
    const float* bih0  = (const float*)d_in[4];
    const float* bhh0  = (const float*)d_in[5];
    const float* Wih1  = (const float*)d_in[6];
    const float* Whh1  = (const float*)d_in[7];
    const float* bih1  = (const float*)d_in[8];
    const float* bhh1  = (const float*)d_in[9];
    float* out = (float*)d_out;

    cudaFuncSetAttribute(rnn_kernel, cudaFuncAttributeMaxDynamicSharedMemorySize, SMEM_BYTES);

    reset_kernel<<<(B_N * H_N + 255) / 256, 256>>>();
    embw_kernel<<<dim3(H_N / 128, V_N / 128), 256>>>(emb, Wih0, bih0, bhh0);
    rnn_kernel<<<GRID_R, NTHR, SMEM_BYTES>>>(input, Whh0, Wih1, Whh1, bih1, bhh1, out);
}

// round 13
// speedup vs baseline: 1.2916x; 1.0325x over previous
#include <cuda_runtime.h>
#include <cstdint>
#include <cstddef>

#define T_N   1024
#define B_N   64
#define V_N   32000
#define H_N   512

#define GC    32                 // col-members per group
#define GB    4                  // independent batch-groups
#define GRID_R (GC * GB)         // 128 CTAs, 1 per SM
#define BPG   16                 // batches per group
#define CPM   16                 // cols per member
#define NTHR  256
#define NSTEP (T_N + 3)

// ---------------- persistent device scratch ----------------
__device__ float    g_embW0[(size_t)V_N * H_N];   // emb @ Wih0^T + bih0 + bhh0
__device__ float    g_h0[2][B_N * H_N];
__device__ float    g_h1[2][B_N * H_N];
__device__ unsigned g_bar[GB][NSTEP];             // per-(group,step) arrival counters

// ---------------- packed-fp32 helpers ----------------
typedef unsigned long long u64;
__device__ __forceinline__ u64 ffma2(u64 a, u64 b, u64 c) {
    u64 d;
    asm("fma.rn.f32x2 %0, %1, %2, %3;" : "=l"(d) : "l"(a), "l"(b), "l"(c));
    return d;
}
__device__ __forceinline__ float unpack_sum(u64 a) {
    float lo, hi;
    asm("mov.b64 {%0, %1}, %2;" : "=f"(lo), "=f"(hi) : "l"(a));
    return lo + hi;
}
__device__ __forceinline__ u64 dup2(float a) {
    u64 d;
    asm("mov.b64 %0, {%1, %1};" : "=l"(d) : "f"(a));
    return d;
}
__device__ __forceinline__ void unpack2(u64 a, float& lo, float& hi) {
    asm("mov.b64 {%0, %1}, %2;" : "=f"(lo), "=f"(hi) : "l"(a));
}

// ---------------- reset: deterministic per launch / graph replay ----------------
__global__ void reset_kernel() {
    int i = blockIdx.x * blockDim.x + threadIdx.x;
    if (i < B_N * H_N) {
        g_h0[0][i] = 0.f; g_h0[1][i] = 0.f;
        g_h1[0][i] = 0.f; g_h1[1][i] = 0.f;
    }
    if (i < GB * NSTEP) {
        int st = i % NSTEP;
        ((unsigned*)g_bar)[i] = (st == 0) ? (unsigned)GC : 0u;  // step-0 pre-passed
    }
}

// ---------------- embW0[v][h] = emb[v]·Wih0[h] + bih0[h] + bhh0[h] (f32x2) ----------------
__global__ __launch_bounds__(256) void embw_kernel(const float* __restrict__ A,
                                                   const float* __restrict__ W,
                                                   const float* __restrict__ bih,
                                                   const float* __restrict__ bhh) {
    __shared__ float As[8][132];
    __shared__ float Ws[8][132];
    const int tid   = threadIdx.x;
    const int hBase = blockIdx.x * 128;
    const int vBase = blockIdx.y * 128;
    const int lRow  = tid >> 1;
    const int lCol  = (tid & 1) * 4;
    const int tx    = tid & 15;
    const int ty    = tid >> 4;

    const float4* Ap = (const float4*)(A + (size_t)(vBase + lRow) * H_N + lCol);
    const float4* Wp = (const float4*)(W + (size_t)(hBase + lRow) * H_N + lCol);

    u64 acc[8][4];
#pragma unroll
    for (int i = 0; i < 8; i++)
#pragma unroll
        for (int j = 0; j < 4; j++) acc[i][j] = 0ull;

    float4 av = Ap[0];
    float4 wv = Wp[0];

    for (int k0 = 0; k0 < 512; k0 += 8) {
        __syncthreads();
        As[lCol + 0][lRow] = av.x; As[lCol + 1][lRow] = av.y;
        As[lCol + 2][lRow] = av.z; As[lCol + 3][lRow] = av.w;
        Ws[lCol + 0][lRow] = wv.x; Ws[lCol + 1][lRow] = wv.y;
        Ws[lCol + 2][lRow] = wv.z; Ws[lCol + 3][lRow] = wv.w;
        __syncthreads();
        if (k0 + 8 < 512) {
            av = Ap[(k0 + 8) >> 2];
            wv = Wp[(k0 + 8) >> 2];
        }
#pragma unroll
        for (int k = 0; k < 8; k++) {
            float a[8];
            *(float4*)&a[0] = *(const float4*)&As[k][ty * 8];
            *(float4*)&a[4] = *(const float4*)&As[k][ty * 8 + 4];
            ulonglong2 wp0 = *(const ulonglong2*)&Ws[k][tx * 8];
            ulonglong2 wp1 = *(const ulonglong2*)&Ws[k][tx * 8 + 4];
            u64 wq[4] = { wp0.x, wp0.y, wp1.x, wp1.y };
#pragma unroll
            for (int i = 0; i < 8; i++) {
                u64 a2 = dup2(a[i]);
#pragma unroll
                for (int j = 0; j < 4; j++) acc[i][j] = ffma2(a2, wq[j], acc[i][j]);
            }
        }
    }

#pragma unroll
    for (int i = 0; i < 8; i++) {
        const int v = vBase + ty * 8 + i;
        float* orow = &g_embW0[(size_t)v * H_N + hBase + tx * 8];
        float o[8];
#pragma unroll
        for (int j = 0; j < 4; j++) {
            float lo, hi;
            unpack2(acc[i][j], lo, hi);
            int h = hBase + tx * 8 + j * 2;
            o[j * 2 + 0] = lo + __ldg(&bih[h + 0]) + __ldg(&bhh[h + 0]);
            o[j * 2 + 1] = hi + __ldg(&bih[h + 1]) + __ldg(&bhh[h + 1]);
        }
        *(float4*)&orow[0] = *(float4*)&o[0];
        *(float4*)&orow[4] = *(float4*)&o[4];
    }
}

// ---------------- persistent recurrence kernel (R12 core, leaner waits) ----------------
// SMEM floats: W0[8192] WA[8192] WB[8192] Hs0[8192] Hs1[8192] Rs0[4352] Rs1[4352] b1[16]
#define OFF_W0 0
#define OFF_WA 8192
#define OFF_WB 16384
#define OFF_H0 24576
#define OFF_H1 32768
#define OFF_R0 40960
#define OFF_R1 (OFF_R0 + 4352)
#define OFF_B1 (OFF_R1 + 4352)
#define SMEM_FLOATS (OFF_B1 + 16)
#define SMEM_BYTES  (SMEM_FLOATS * 4)       // ~198.7 KB

__global__ __launch_bounds__(NTHR, 1) void rnn_kernel(const int*   __restrict__ input,
                                                      const float* __restrict__ Whh0,
                                                      const float* __restrict__ Wih1,
                                                      const float* __restrict__ Whh1,
                                                      const float* __restrict__ bih1,
                                                      const float* __restrict__ bhh1,
                                                      float*       __restrict__ out) {
    extern __shared__ float smem[];
    float* W0s = smem + OFF_W0;
    float* WAs = smem + OFF_WA;
    float* WBs = smem + OFF_WB;
    float* Rs0 = smem + OFF_R0;
    float* Rs1 = smem + OFF_R1;
    float* b1s = smem + OFF_B1;

    const int tid  = threadIdx.x;
    const int cid  = blockIdx.x;
    const int m    = cid & (GC - 1);   // member: cols [m*16, m*16+16)
    const int grp  = cid >> 5;         // group: batches [grp*16, grp*16+16)
    const int gb16 = grp * BPG;
    const int w    = tid >> 5;
    const int lane = tid & 31;
    const int o    = w >> 2;           // batch-oct (0..1)
    const int cq   = w & 3;            // col-quad  (0..3)

    // ---- preload weight slices: rows [m*16, m*16+16) ----
    {
        const float4* s0 = (const float4*)Whh0 + (size_t)m * 2048;
        const float4* s1 = (const float4*)Wih1 + (size_t)m * 2048;
        const float4* s2 = (const float4*)Whh1 + (size_t)m * 2048;
        float4* d0 = (float4*)W0s; float4* d1 = (float4*)WAs; float4* d2 = (float4*)WBs;
        for (int r = tid; r < 2048; r += NTHR) {
            d0[r] = __ldg(&s0[r]);
            d1[r] = __ldg(&s1[r]);
            d2[r] = __ldg(&s2[r]);
        }
        if (tid < CPM) b1s[tid] = __ldg(&bih1[m * CPM + tid]) + __ldg(&bhh1[m * CPM + tid]);
    }
    __syncthreads();

    // read-phase decode: thread tid owns output tid = b*16 + c
    const int b_out  = gb16 + (tid >> 4);
    const int c_glob = m * CPM + (tid & 15);

    const ulonglong2* W0u = (const ulonglong2*)W0s;
    const ulonglong2* WAu = (const ulonglong2*)WAs;
    const ulonglong2* WBu = (const ulonglong2*)WBs;
    const ulonglong2* H0u = (const ulonglong2*)(smem + OFF_H0);
    const ulonglong2* H1u = (const ulonglong2*)(smem + OFF_H1);
    const unsigned sd0 = (unsigned)__cvta_generic_to_shared(smem + OFF_H0);
    const unsigned sd1 = (unsigned)__cvta_generic_to_shared(smem + OFF_H1);

    u64 acc0[8][4], accA[8][4];

    // fused pass-1 body on preloaded weights (k-quarter J)
#define MMA1_BODY(J, W0Q, WAQ)                                                   \
    {                                                                            \
        _Pragma("unroll")                                                        \
        for (int i = 0; i < 8; i++) {                                            \
            ulonglong2 hv = H0u[(o * 8 + i) * 128 + (J) * 32 + lane];            \
            _Pragma("unroll")                                                    \
            for (int c = 0; c < 4; c++) {                                        \
                acc0[i][c] = ffma2(hv.x, W0Q[c].x, acc0[i][c]);                  \
                acc0[i][c] = ffma2(hv.y, W0Q[c].y, acc0[i][c]);                  \
                accA[i][c] = ffma2(hv.x, WAQ[c].x, accA[i][c]);                  \
                accA[i][c] = ffma2(hv.y, WAQ[c].y, accA[i][c]);                  \
            }                                                                    \
        }                                                                        \
    }

#define LOAD_W1(J, W0Q, WAQ)                                                     \
    _Pragma("unroll")                                                            \
    for (int c = 0; c < 4; c++) {                                                \
        int row = cq * 4 + c;                                                    \
        W0Q[c] = W0u[row * 128 + (J) * 32 + lane];                               \
        WAQ[c] = WAu[row * 128 + (J) * 32 + lane];                               \
    }

    // pass-2 chunk body
#define MMA2_BODY(J, WBQ)                                                        \
    {                                                                            \
        _Pragma("unroll")                                                        \
        for (int i = 0; i < 8; i++) {                                            \
            ulonglong2 hv = H1u[(o * 8 + i) * 128 + (J) * 32 + lane];            \
            _Pragma("unroll")                                                    \
            for (int c = 0; c < 4; c++) {                                        \
                accA[i][c] = ffma2(hv.x, WBQ[c].x, accA[i][c]);                  \
                accA[i][c] = ffma2(hv.y, WBQ[c].y, accA[i][c]);                  \
            }                                                                    \
        }                                                                        \
    }

#define LOAD_W2(J, WBQ)                                                          \
    _Pragma("unroll")                                                            \
    for (int c = 0; c < 4; c++)                                                  \
        WBQ[c] = WBu[(cq * 4 + c) * 128 + (J) * 32 + lane];

    // shfl-16 pre-reduce ACC -> RS rows of 16 (stride 17, conflict-free)
#define REDUCE_TO(RS, ACC)                                                       \
    _Pragma("unroll")                                                            \
    for (int i = 0; i < 8; i++)                                                  \
        _Pragma("unroll")                                                        \
        for (int c = 0; c < 4; c++) {                                            \
            float v = unpack_sum(ACC[i][c]);                                     \
            v += __shfl_xor_sync(0xffffffffu, v, 16);                            \
            if (lane < 16)                                                       \
                (RS)[((o * 8 + i) * 16 + cq * 4 + c) * 17 + lane] = v;           \
        }

    // stage a full 16-row block as ONE commit group
#define STAGE_FULL(SD, SRC)                                                      \
    {                                                                            \
        _Pragma("unroll")                                                        \
        for (int r = 0; r < 8; r++) {                                            \
            int l   = r * NTHR + tid;          /* 0..2047 f4 */                  \
            int b_l = l >> 7;                                                    \
            int c4  = l & 127;                                                   \
            size_t srcf4 = (size_t)(gb16 + b_l) * 128 + c4;                      \
            asm volatile("cp.async.cg.shared.global [%0], [%1], 16;\n"           \
                         :: "r"((SD) + l * 16), "l"((SRC) + srcf4 * 4));         \
        }                                                                        \
        asm volatile("cp.async.commit_group;\n");                                \
    }

    for (int s = 1; s <= T_N + 1; s++) {
        const bool doH0 = (s <= T_N);
        const bool doH1 = (s >= 2);

        // ---- gather input-projection value early (independent) ----
        float xw = 0.f;
        if (doH0) {
            int tok = __ldg(&input[(s - 1) * B_N + b_out]);
            xw = __ldcg(&g_embW0[(size_t)tok * H_N + c_glob]);
        }

        // ---- barrier: single-counter wait (tid 0 polls one address) ----
        if (tid == 0) {
            const unsigned* bp = &g_bar[grp][s - 1];
            unsigned v;
            do {
                asm volatile("ld.acquire.gpu.global.u32 %0, [%1];"
                             : "=r"(v) : "l"(bp) : "memory");
            } while (v < (unsigned)GC);
        }
        __syncthreads();

        // ---- stage h0[s-2] (group 0) and h1[s-3] (group 1) ----
        STAGE_FULL(sd0, g_h0[s & 1])
        STAGE_FULL(sd1, g_h1[(s + 1) & 1])

#pragma unroll
        for (int i = 0; i < 8; i++)
#pragma unroll
            for (int c = 0; c < 4; c++) { acc0[i][c] = 0ull; accA[i][c] = 0ull; }

        // ---- hoist chunk-0 weights into the h0-stage wait bubble ----
        ulonglong2 w0q[4], waq[4];
        LOAD_W1(0, w0q, waq)
        asm volatile("cp.async.wait_group 1;\n" ::: "memory");
        __syncthreads();

        // ---- pass 1 (fused Whh0 + Wih1 on h0[s-2]) ----
        MMA1_BODY(0, w0q, waq)
        LOAD_W1(1, w0q, waq)
        MMA1_BODY(1, w0q, waq)
        LOAD_W1(2, w0q, waq)
        MMA1_BODY(2, w0q, waq)
        LOAD_W1(3, w0q, waq)
        MMA1_BODY(3, w0q, waq)

        // ---- hoist pass-2 chunk-0 weights into the h1-stage wait bubble ----
        ulonglong2 wbq[4];
        LOAD_W2(0, wbq)
        asm volatile("cp.async.wait_group 0;\n" ::: "memory");
        __syncthreads();

        // ---- pass 2 (Whh1 on h1[s-3]) ----
        MMA2_BODY(0, wbq)
        LOAD_W2(1, wbq)
        MMA2_BODY(1, wbq)
        LOAD_W2(2, wbq)
        MMA2_BODY(2, wbq)
        LOAD_W2(3, wbq)
        MMA2_BODY(3, wbq)

        // ---- merged reduce (one sync for both) ----
        REDUCE_TO(Rs0, acc0)
        REDUCE_TO(Rs1, accA)
        __syncthreads();

        // ---- epilogues ----
        if (doH0) {
            float ssum = 0.f;
#pragma unroll
            for (int l = 0; l < 16; l++) ssum += Rs0[tid * 17 + l];
            __stcg(&g_h0[(s - 1) & 1][b_out * H_N + c_glob], tanhf(ssum + xw));
        }
        if (doH1) {
            float ssum = 0.f;
#pragma unroll
            for (int l = 0; l < 16; l++) ssum += Rs1[tid * 17 + l];
            float v = tanhf(ssum + b1s[tid & 15]);
            __stcg(&g_h1[s & 1][b_out * H_N + c_glob], v);
            if (s == T_N + 1) __stcg(&out[b_out * H_N + c_glob], v);
        }

        // ---- publish: one release-reduction on the group counter ----
        __syncthreads();
        if (tid == 0)
            asm volatile("red.release.gpu.global.add.u32 [%0], 1;"
                         :: "l"(&g_bar[grp][s]) : "memory");
    }
#undef MMA1_BODY
#undef LOAD_W1
#undef MMA2_BODY
#undef LOAD_W2
#undef REDUCE_TO
#undef STAGE_FULL
}

// ---------------- launch ----------------
extern "C" void kernel_launch(void* const* d_in, const int* in_sizes, int n_in,
                              void* d_out, int out_size) {
    const int*   input = (const int*)  d_in[0];
    const float* emb   = (const float*)d_in[1];
    const float* Wih0  = (const float*)d_in[2];
    const float* Whh0  = (const float*)d_in[3];
    const float* bih0  = (const float*)d_in[4];
    const float* bhh0  = (const float*)d_in[5];
    const float* Wih1  = (const float*)d_in[6];
    const float* Whh1  = (const float*)d_in[7];
    const float* bih1  = (const float*)d_in[8];
    const float* bhh1  = (const float*)d_in[9];
    float* out = (float*)d_out;

    cudaFuncSetAttribute(rnn_kernel, cudaFuncAttributeMaxDynamicSharedMemorySize, SMEM_BYTES);

    reset_kernel<<<(B_N * H_N + 255) / 256, 256>>>();
    embw_kernel<<<dim3(H_N / 128, V_N / 128), 256>>>(emb, Wih0, bih0, bhh0);
    rnn_kernel<<<GRID_R, NTHR, SMEM_BYTES>>>(input, Whh0, Wih1, Whh1, bih1, bhh1, out);
}